// round 4
// baseline (speedup 1.0000x reference)
#include <cuda_runtime.h>
#include <math.h>

// Problem constants
#define Bc 4
#define Tc 2048
#define Ec 64
#define Hc 8
#define QLc 6
#define BHc (Bc*Hc)
#define CAPU 384         // max positions per row (12 per 64-chunk * 32, dense <=384)

// rem-set S = {0..7, 9, 13, 21, 37}
#define REMMASK (0xFFull | (1ull<<9) | (1ull<<13) | (1ull<<21) | (1ull<<37))

// Static device scratch (allocation-free rule)
__device__ float g_Q[BHc*Tc*Ec];     // [b,h,t,e]
__device__ float g_K[BHc*Tc*Ec];
__device__ float g_V[BHc*Tc*Ec];
__device__ float g_ATT[BHc*Tc*Ec];

// ---------------------------------------------------------------------------
// V projection: value = x @ Wv + bv, stored as [b,h,t,e]
// ---------------------------------------------------------------------------
__global__ void proj_v(const float* __restrict__ x,
                       const float* __restrict__ Wv,
                       const float* __restrict__ bv) {
    int bt = blockIdx.x;
    __shared__ float xs[Ec];
    int tid = threadIdx.x;              // 128 threads
    if (tid < Ec) xs[tid] = x[(size_t)bt * Ec + tid];
    __syncthreads();
    float acc[4] = {0.f, 0.f, 0.f, 0.f};
    for (int i = 0; i < Ec; i++) {
        float xv = xs[i];
        const float* wr = Wv + (size_t)i * (Hc * Ec);
        #pragma unroll
        for (int a = 0; a < 4; a++) acc[a] += xv * wr[tid + a * 128];
    }
    int b = bt / Tc, t = bt % Tc;
    #pragma unroll
    for (int a = 0; a < 4; a++) {
        int o = tid + a * 128;
        int h = o >> 6, e = o & 63;
        g_V[(((size_t)b * Hc + h) * Tc + t) * Ec + e] = acc[a] + bv[o];
    }
}

// ---------------------------------------------------------------------------
// Causal conv1d QK projection: 16-ch x 64-t tile, 64 threads, 4o x 4t blocking
// ---------------------------------------------------------------------------
__global__ void proj_qk(const float* __restrict__ x,
                        const float* __restrict__ Wqk,
                        const float* __restrict__ bqk) {
    __shared__ float Ws[16][385];   // kk = j*64 + i ordering
    __shared__ float Xs[69][65];    // rows t0-5 .. t0+63
    int b  = blockIdx.z;
    int o0 = blockIdx.y * 16;
    int t0 = blockIdx.x * 64;
    int tid = threadIdx.x;          // 64

    for (int idx = tid; idx < 16 * 384; idx += 64) {
        int oo = idx / 384, kk = idx % 384;
        int j = kk >> 6, i = kk & 63;
        Ws[oo][kk] = Wqk[(size_t)(o0 + oo) * 384 + i * QLc + j];
    }
    for (int idx = tid; idx < 69 * 64; idx += 64) {
        int rr = idx >> 6, i = idx & 63;
        int t = t0 - 5 + rr;
        Xs[rr][i] = (t >= 0) ? x[((size_t)b * Tc + t) * Ec + i] : 0.f;
    }
    __syncthreads();

    int ox = tid & 3;    // 4 groups, 4 channels each
    int tx = tid >> 2;   // 16 groups, 4 timesteps each
    float acc[4][4];
    #pragma unroll
    for (int a = 0; a < 4; a++)
        #pragma unroll
        for (int bb = 0; bb < 4; bb++) acc[a][bb] = 0.f;

    for (int kk = 0; kk < 384; kk++) {
        int j = kk >> 6, i = kk & 63;
        float wv[4], xv[4];
        #pragma unroll
        for (int a = 0; a < 4; a++) wv[a] = Ws[ox * 4 + a][kk];
        #pragma unroll
        for (int bb = 0; bb < 4; bb++) xv[bb] = Xs[tx * 4 + bb + j][i];
        #pragma unroll
        for (int a = 0; a < 4; a++)
            #pragma unroll
            for (int bb = 0; bb < 4; bb++) acc[a][bb] += wv[a] * xv[bb];
    }
    #pragma unroll
    for (int a = 0; a < 4; a++) {
        int ch = o0 + ox * 4 + a;
        float bias = bqk[ch];
        int hh = (ch & 511) >> 6, e = ch & 63;
        float* dst = (ch < 512 ? g_Q : g_K) +
                     ((size_t)b * Hc + hh) * Tc * Ec + e;
        #pragma unroll
        for (int bb = 0; bb < 4; bb++) {
            int t = t0 + tx * 4 + bb;
            dst[(size_t)t * Ec] = acc[a][bb] + bias;
        }
    }
}

// ---------------------------------------------------------------------------
// Attention: warp handles 8 consecutive query rows (row-octet) for one bh.
// Membership by closed-form predicate; K/V loaded once per union column and
// reused across 8 rows in registers. sc[warp][row][pos] holds scores/weights.
// ---------------------------------------------------------------------------
__device__ __forceinline__ bool member_sp(int ri, int s, int c) {
    if (s < 0 || s > 37 || c < 0) return false;
    if (!((REMMASK >> s) & 1ull)) return false;
    int j = ri & 63;
    if (j < 5 && c == j) return false;   // exclusive-terminal edge case
    return true;
}
__device__ __forceinline__ int rank_of(int s) {
    return __popcll(REMMASK & ((1ull << s) - 1ull));
}
__device__ __forceinline__ int s_of_rank(int rk) {   // inverse of rank_of on S
    if (rk < 8) return rk;
    if (rk == 8) return 9;
    if (rk == 9) return 13;
    if (rk == 10) return 21;
    return 37;
}
__device__ __forceinline__ int urem(int j) {         // union rem table (40, padded)
    return (j <= 28) ? j : ((j <= 36) ? j + 8 : 63);
}

__global__ __launch_bounds__(128) void attn2(float* __restrict__ wout_base) {
    __shared__ float sc[4][8][CAPU];
    int w = threadIdx.x >> 5;
    int lane = threadIdx.x & 31;
    int sub = lane & 7;        // e-chunk owner
    int grp = lane >> 3;       // column group 0..3
    int g = 255 - (blockIdx.x * 4 + w);   // heavy groups first
    int bh = blockIdx.y;
    int r0 = g * 8;
    bool dense = (r0 < 384);

    const float* Qb = g_Q + (size_t)bh * Tc * Ec;
    const float* Kb = g_K + (size_t)bh * Tc * Ec;
    const float* Vb = g_V + (size_t)bh * Tc * Ec;
    float* wbase = wout_base + ((size_t)bh * Tc + r0) * Tc;

    // Zero the 8 output weight rows (replaces global memset)
    {
        float4 z4 = make_float4(0.f, 0.f, 0.f, 0.f);
        #pragma unroll
        for (int i = 0; i < 8; i++) {
            float4* p = (float4*)(wbase + (size_t)i * Tc);
            #pragma unroll
            for (int s = 0; s < 16; s++) p[s * 32 + lane] = z4;
        }
    }

    // Q registers: q[i][0..7] = Q[r0+i][sub*8 .. sub*8+7]
    float q[8][8];
    #pragma unroll
    for (int i = 0; i < 8; i++) {
        const float4* qp = (const float4*)(Qb + (size_t)(r0 + i) * Ec + sub * 8);
        float4 a = qp[0], b = qp[1];
        q[i][0]=a.x; q[i][1]=a.y; q[i][2]=a.z; q[i][3]=a.w;
        q[i][4]=b.x; q[i][5]=b.y; q[i][6]=b.z; q[i][7]=b.w;
    }

    int top0 = r0 + 7;

    // ---- Phase 1: scores ----
    if (dense) {
        for (int c0 = 0; c0 <= top0; c0 += 4) {
            int c = c0 + grp;
            int cc = c <= top0 ? c : top0;
            const float4* kp = (const float4*)(Kb + (size_t)cc * Ec + sub * 8);
            float4 ka = kp[0], kb = kp[1];
            float p[8];
            #pragma unroll
            for (int i = 0; i < 8; i++)
                p[i] = q[i][0]*ka.x + q[i][1]*ka.y + q[i][2]*ka.z + q[i][3]*ka.w
                     + q[i][4]*kb.x + q[i][5]*kb.y + q[i][6]*kb.z + q[i][7]*kb.w;
            #pragma unroll
            for (int off = 1; off <= 4; off <<= 1)
                #pragma unroll
                for (int i = 0; i < 8; i++)
                    p[i] += __shfl_xor_sync(0xffffffffu, p[i], off);
            int i = sub, ri = r0 + i;
            if (c <= ri) sc[w][i][c] = p[i] * 0.125f;
        }
    } else {
        int nch = top0 >> 6;
        for (int k = 0; k <= nch; k++) {
            int top = top0 - 64 * k;
            for (int j0 = 0; j0 < 40; j0 += 4) {
                int rem = urem(j0 + grp);
                int c = top - rem;
                int cc = c >= 0 ? c : 0;
                const float4* kp = (const float4*)(Kb + (size_t)cc * Ec + sub * 8);
                float4 ka = kp[0], kb = kp[1];
                float p[8];
                #pragma unroll
                for (int i = 0; i < 8; i++)
                    p[i] = q[i][0]*ka.x + q[i][1]*ka.y + q[i][2]*ka.z + q[i][3]*ka.w
                         + q[i][4]*kb.x + q[i][5]*kb.y + q[i][6]*kb.z + q[i][7]*kb.w;
                #pragma unroll
                for (int off = 1; off <= 4; off <<= 1)
                    #pragma unroll
                    for (int i = 0; i < 8; i++)
                        p[i] += __shfl_xor_sync(0xffffffffu, p[i], off);
                int i = sub, ri = r0 + i;
                int s = rem - (7 - i);
                if (member_sp(ri, s, c))
                    sc[w][i][12 * k + rank_of(s)] = p[i] * 0.125f;
            }
        }
    }
    __syncwarp();

    // ---- Phase 2+3: per-row softmax + scatter normalized weights ----
    for (int i = 0; i < 8; i++) {
        int ri = r0 + i;
        int npos = dense ? (ri + 1) : (12 * (ri >> 6) + 12);
        float m = -1e30f;
        for (int pos = lane; pos < npos; pos += 32) {
            bool valid; 
            if (dense) valid = true;
            else {
                int k = pos / 12, rk = pos - 12 * k;
                int s = s_of_rank(rk);
                int c = ri - 64 * k - s;
                int j = ri & 63;
                valid = (c >= 0) && !(j < 5 && c == j);
            }
            if (valid) m = fmaxf(m, sc[w][i][pos]);
        }
        #pragma unroll
        for (int off = 16; off; off >>= 1)
            m = fmaxf(m, __shfl_xor_sync(0xffffffffu, m, off));
        float sum = 0.f;
        for (int pos = lane; pos < npos; pos += 32) {
            bool valid;
            if (dense) valid = true;
            else {
                int k = pos / 12, rk = pos - 12 * k;
                int s = s_of_rank(rk);
                int c = ri - 64 * k - s;
                int j = ri & 63;
                valid = (c >= 0) && !(j < 5 && c == j);
            }
            if (valid) {
                float e = __expf(sc[w][i][pos] - m);
                sc[w][i][pos] = e;
                sum += e;
            }
        }
        #pragma unroll
        for (int off = 16; off; off >>= 1)
            sum += __shfl_xor_sync(0xffffffffu, sum, off);
        float inv = __fdividef(1.f, sum);
        float* wrow = wbase + (size_t)i * Tc;
        for (int pos = lane; pos < npos; pos += 32) {
            bool valid; int c;
            if (dense) { valid = true; c = pos; }
            else {
                int k = pos / 12, rk = pos - 12 * k;
                int s = s_of_rank(rk);
                c = ri - 64 * k - s;
                int j = ri & 63;
                valid = (c >= 0) && !(j < 5 && c == j);
            }
            if (valid) {
                float nw = sc[w][i][pos] * inv;
                sc[w][i][pos] = nw;     // keep for PV
                wrow[c] = nw;
            }
        }
    }
    __syncwarp();

    // ---- Phase 4: PV, V reused across 8 rows ----
    float acc[8][8];
    #pragma unroll
    for (int i = 0; i < 8; i++)
        #pragma unroll
        for (int jj = 0; jj < 8; jj++) acc[i][jj] = 0.f;

    if (dense) {
        for (int c0 = 0; c0 <= top0; c0 += 4) {
            int c = c0 + grp;
            int cc = c <= top0 ? c : top0;
            const float4* vp = (const float4*)(Vb + (size_t)cc * Ec + sub * 8);
            float4 va = vp[0], vb = vp[1];
            #pragma unroll
            for (int i = 0; i < 8; i++) {
                int ri = r0 + i;
                if (c <= ri) {
                    float wg = sc[w][i][c];
                    acc[i][0] += wg*va.x; acc[i][1] += wg*va.y;
                    acc[i][2] += wg*va.z; acc[i][3] += wg*va.w;
                    acc[i][4] += wg*vb.x; acc[i][5] += wg*vb.y;
                    acc[i][6] += wg*vb.z; acc[i][7] += wg*vb.w;
                }
            }
        }
    } else {
        int nch = top0 >> 6;
        for (int k = 0; k <= nch; k++) {
            int top = top0 - 64 * k;
            for (int j0 = 0; j0 < 40; j0 += 4) {
                int rem = urem(j0 + grp);
                int c = top - rem;
                int cc = c >= 0 ? c : 0;
                const float4* vp = (const float4*)(Vb + (size_t)cc * Ec + sub * 8);
                float4 va = vp[0], vb = vp[1];
                #pragma unroll
                for (int i = 0; i < 8; i++) {
                    int ri = r0 + i;
                    int s = rem - (7 - i);
                    if (member_sp(ri, s, c)) {
                        float wg = sc[w][i][12 * k + rank_of(s)];
                        acc[i][0] += wg*va.x; acc[i][1] += wg*va.y;
                        acc[i][2] += wg*va.z; acc[i][3] += wg*va.w;
                        acc[i][4] += wg*vb.x; acc[i][5] += wg*vb.y;
                        acc[i][6] += wg*vb.z; acc[i][7] += wg*vb.w;
                    }
                }
            }
        }
    }
    // reduce partial accumulators across the 4 column-groups
    #pragma unroll
    for (int off = 8; off <= 16; off <<= 1)
        #pragma unroll
        for (int i = 0; i < 8; i++)
            #pragma unroll
            for (int jj = 0; jj < 8; jj++)
                acc[i][jj] += __shfl_xor_sync(0xffffffffu, acc[i][jj], off);
    if (grp == 0) {
        #pragma unroll
        for (int i = 0; i < 8; i++) {
            float* dst = g_ATT + ((size_t)bh * Tc + r0 + i) * Ec + sub * 8;
            float4 o0 = make_float4(acc[i][0], acc[i][1], acc[i][2], acc[i][3]);
            float4 o1 = make_float4(acc[i][4], acc[i][5], acc[i][6], acc[i][7]);
            ((float4*)dst)[0] = o0;
            ((float4*)dst)[1] = o1;
        }
    }
}

// ---------------------------------------------------------------------------
// Output projection: out[b,t,:] = attn_flat[b,t,:] @ Wp + bp
// ---------------------------------------------------------------------------
__global__ void proj_out(const float* __restrict__ Wp,
                         const float* __restrict__ bp,
                         float* __restrict__ out) {
    __shared__ float as[4][520];
    int base_bt = blockIdx.x * 4;
    int tid = threadIdx.x;   // 256
    for (int idx = tid; idx < 4 * 512; idx += 256) {
        int rr = idx >> 9, c = idx & 511;
        int bt = base_bt + rr;
        int b = bt / Tc, t = bt % Tc;
        int h = c >> 6, e = c & 63;
        as[rr][c] = g_ATT[(((size_t)b * Hc + h) * Tc + t) * Ec + e];
    }
    __syncthreads();
    int rr = tid >> 6, eo = tid & 63;
    float acc = bp[eo];
    for (int c = 0; c < 512; c++)
        acc += as[rr][c] * Wp[(size_t)c * Ec + eo];
    out[(size_t)(base_bt + rr) * Ec + eo] = acc;
}

// ---------------------------------------------------------------------------
extern "C" void kernel_launch(void* const* d_in, const int* in_sizes, int n_in,
                              void* d_out, int out_size) {
    const float* x    = (const float*)d_in[0];
    const float* Wqk  = (const float*)d_in[1];
    const float* bqk  = (const float*)d_in[2];
    const float* Wv   = (const float*)d_in[3];
    const float* bv   = (const float*)d_in[4];
    const float* Wp   = (const float*)d_in[5];
    const float* bp   = (const float*)d_in[6];
    // d_in[7] (mask) unused: membership regenerated by closed-form predicate.

    float* out = (float*)d_out;
    float* weights = out + (size_t)Bc * Tc * Ec;  // attn_weights after out

    proj_v<<<Bc * Tc, 128>>>(x, Wv, bv);
    dim3 gqk(Tc / 64, 1024 / 16, Bc);
    proj_qk<<<gqk, 64>>>(x, Wqk, bqk);
    attn2<<<dim3(64, 32), 128>>>(weights);
    proj_out<<<Bc * Tc / 4, 256>>>(Wp, bp, out);
}

// round 5
// speedup vs baseline: 1.2847x; 1.2847x over previous
#include <cuda_runtime.h>
#include <math.h>

#define Bc 4
#define Tc 2048
#define Ec 64
#define Hc 8
#define QLc 6
#define BHc (Bc*Hc)
#define CAPU 385   // 384 positions max, padded to break smem bank aliasing

// rem-set S = {0..7, 9, 13, 21, 37}: member(r,c) <=> ((r-c) mod 64) in S (sparse rows)
#define REMMASK (0xFFull | (1ull<<9) | (1ull<<13) | (1ull<<21) | (1ull<<37))

__device__ float g_Q[BHc*Tc*Ec];
__device__ float g_K[BHc*Tc*Ec];
__device__ float g_V[BHc*Tc*Ec];
__device__ float g_ATT[BHc*Tc*Ec];

// ---- f32x2 packed FMA (PTX-only; two independent exact fp32 FMAs) ----
__device__ __forceinline__ float2 ffma2(float2 a, float2 b, float2 c) {
    float2 d;
    asm("fma.rn.f32x2 %0, %1, %2, %3;"
        : "=l"(*(unsigned long long*)&d)
        : "l"(*(unsigned long long*)&a),
          "l"(*(unsigned long long*)&b),
          "l"(*(unsigned long long*)&c));
    return d;
}
__device__ __forceinline__ float2 shfl_xor_f2(float2 v, int off) {
    unsigned long long u = *(unsigned long long*)&v;
    u = __shfl_xor_sync(0xffffffffu, u, off);
    return *(float2*)&u;
}

// ---------------------------------------------------------------------------
// V projection, tiled: block = 8 bt-rows x 512 outputs, 128 threads.
// ---------------------------------------------------------------------------
__global__ void proj_v(const float* __restrict__ x,
                       const float* __restrict__ Wv,
                       const float* __restrict__ bv) {
    __shared__ float xs[8][64];
    int bt0 = blockIdx.x * 8;
    int tid = threadIdx.x;    // 128
    {
        int m = tid >> 4, i = (tid << 2) & 63;
        *(float4*)&xs[m][i] = *(const float4*)(x + (size_t)(bt0 + m) * Ec + i);
    }
    __syncthreads();
    int nc = tid * 4;
    float2 acc[8][2];
    #pragma unroll
    for (int m = 0; m < 8; m++) { acc[m][0] = make_float2(0.f,0.f); acc[m][1] = make_float2(0.f,0.f); }
    for (int i = 0; i < 64; i++) {
        float4 w4 = *(const float4*)(Wv + (size_t)i * 512 + nc);
        float2 wa = make_float2(w4.x, w4.y), wb = make_float2(w4.z, w4.w);
        #pragma unroll
        for (int m = 0; m < 8; m++) {
            float xm = xs[m][i];
            float2 x2 = make_float2(xm, xm);
            acc[m][0] = ffma2(x2, wa, acc[m][0]);
            acc[m][1] = ffma2(x2, wb, acc[m][1]);
        }
    }
    float4 bb4 = *(const float4*)(bv + nc);
    int h = nc >> 6, e = nc & 63;
    int b = bt0 / Tc;
    #pragma unroll
    for (int m = 0; m < 8; m++) {
        int t = (bt0 & (Tc - 1)) + m;
        float4 o = make_float4(acc[m][0].x + bb4.x, acc[m][0].y + bb4.y,
                               acc[m][1].x + bb4.z, acc[m][1].y + bb4.w);
        *(float4*)(g_V + (((size_t)b * Hc + h) * Tc + t) * Ec + e) = o;
    }
}

// ---------------------------------------------------------------------------
// Causal conv1d QK projection (R3 structure + f32x2 over t-pairs)
// ---------------------------------------------------------------------------
__global__ void proj_qk(const float* __restrict__ x,
                        const float* __restrict__ Wqk,
                        const float* __restrict__ bqk) {
    __shared__ float Ws[16][385];
    __shared__ float Xs[69][65];
    int b  = blockIdx.z;
    int o0 = blockIdx.y * 16;
    int t0 = blockIdx.x * 64;
    int tid = threadIdx.x;   // 128

    for (int idx = tid; idx < 16 * 384; idx += 128) {
        int oo = idx / 384, kk = idx % 384;
        int j = kk >> 6, i = kk & 63;
        Ws[oo][kk] = Wqk[(size_t)(o0 + oo) * 384 + i * QLc + j];
    }
    for (int idx = tid; idx < 69 * 64; idx += 128) {
        int rr = idx >> 6, i = idx & 63;
        int t = t0 - 5 + rr;
        Xs[rr][i] = (t >= 0) ? x[((size_t)b * Tc + t) * Ec + i] : 0.f;
    }
    __syncthreads();

    int ox = tid & 7;    // 8 groups, 2 channels each
    int tx = tid >> 3;   // 16 groups, 4 timesteps each
    float2 acc2[2][2];
    #pragma unroll
    for (int a = 0; a < 2; a++) { acc2[a][0] = make_float2(0.f,0.f); acc2[a][1] = make_float2(0.f,0.f); }

    for (int kk = 0; kk < 384; kk++) {
        int j = kk >> 6, i = kk & 63;
        float w0 = Ws[ox * 2 + 0][kk];
        float w1 = Ws[ox * 2 + 1][kk];
        float2 w00 = make_float2(w0, w0), w11 = make_float2(w1, w1);
        float x0 = Xs[tx * 4 + 0 + j][i], x1 = Xs[tx * 4 + 1 + j][i];
        float x2 = Xs[tx * 4 + 2 + j][i], x3 = Xs[tx * 4 + 3 + j][i];
        float2 x01 = make_float2(x0, x1), x23 = make_float2(x2, x3);
        acc2[0][0] = ffma2(w00, x01, acc2[0][0]);
        acc2[0][1] = ffma2(w00, x23, acc2[0][1]);
        acc2[1][0] = ffma2(w11, x01, acc2[1][0]);
        acc2[1][1] = ffma2(w11, x23, acc2[1][1]);
    }
    #pragma unroll
    for (int a = 0; a < 2; a++) {
        int ch = o0 + ox * 2 + a;
        float bias = bqk[ch];
        int hh = (ch & 511) >> 6, e = ch & 63;
        float* dst = (ch < 512 ? g_Q : g_K) +
                     ((size_t)b * Hc + hh) * Tc * Ec + e;
        float vals[4] = {acc2[a][0].x, acc2[a][0].y, acc2[a][1].x, acc2[a][1].y};
        #pragma unroll
        for (int bb = 0; bb < 4; bb++) {
            int t = t0 + tx * 4 + bb;
            dst[(size_t)t * Ec] = vals[bb] + bias;
        }
    }
}

// ---------------------------------------------------------------------------
// Attention: warp handles 4 consecutive query rows; membership closed-form.
// ---------------------------------------------------------------------------
__device__ __forceinline__ bool member_sp(int ri, int s, int c) {
    if (s < 0 || s > 37 || c < 0) return false;
    if (!((REMMASK >> s) & 1ull)) return false;
    int j = ri & 63;
    if (j < 5 && c == j) return false;   // exclusive-terminal edge case
    return true;
}
__device__ __forceinline__ int rank_of(int s) {
    return __popcll(REMMASK & ((1ull << s) - 1ull));
}
__device__ __forceinline__ int s_of_rank(int rk) {
    if (rk < 8) return rk;
    if (rk == 8) return 9;
    if (rk == 9) return 13;
    if (rk == 10) return 21;
    return 37;
}
// union of S shifted by 0..3: {0..16} u {21..24} u {37..40}; 28 slots (3 dummy)
__device__ __forceinline__ int urem4(int j) {
    return (j <= 16) ? j : ((j <= 20) ? j + 4 : ((j <= 24) ? j + 16 : 63));
}

__global__ __launch_bounds__(128) void attn3(float* __restrict__ wout_base) {
    __shared__ float sc[4][4][CAPU];
    int w = threadIdx.x >> 5;
    int lane = threadIdx.x & 31;
    int sub = lane & 7;        // e-chunk owner
    int grp = lane >> 3;       // column group 0..3
    int g = 511 - (blockIdx.x * 4 + w);   // heavy groups first
    int bh = blockIdx.y;
    int r0 = g * 4;
    bool dense = (r0 < 384);

    const float* Qb = g_Q + (size_t)bh * Tc * Ec;
    const float* Kb = g_K + (size_t)bh * Tc * Ec;
    const float* Vb = g_V + (size_t)bh * Tc * Ec;
    float* wbase = wout_base + ((size_t)bh * Tc + r0) * Tc;

    // Zero the 4 output weight rows (streaming stores; replaces memset)
    {
        float4 z4 = make_float4(0.f, 0.f, 0.f, 0.f);
        #pragma unroll
        for (int i = 0; i < 4; i++) {
            float4* p = (float4*)(wbase + (size_t)i * Tc);
            #pragma unroll
            for (int s = 0; s < 16; s++) __stwt(&p[s * 32 + lane], z4);
        }
    }

    // Q registers: q2[i][0..3] = Q[r0+i][sub*8 .. sub*8+7] as float2 pairs
    float2 q2[4][4];
    #pragma unroll
    for (int i = 0; i < 4; i++) {
        const float4* qp = (const float4*)(Qb + (size_t)(r0 + i) * Ec + sub * 8);
        float4 a = qp[0], b = qp[1];
        q2[i][0] = make_float2(a.x, a.y); q2[i][1] = make_float2(a.z, a.w);
        q2[i][2] = make_float2(b.x, b.y); q2[i][3] = make_float2(b.z, b.w);
    }
    int top0 = r0 + 3;
    const float2 zero2 = make_float2(0.f, 0.f);

    // ---- Phase 1: scores ----
    if (dense) {
        for (int c0 = 0; c0 <= top0; c0 += 4) {
            int c = c0 + grp;
            int cc = c <= top0 ? c : top0;
            const float4* kp = (const float4*)(Kb + (size_t)cc * Ec + sub * 8);
            float4 ka = kp[0], kb = kp[1];
            float2 k0 = make_float2(ka.x, ka.y), k1 = make_float2(ka.z, ka.w);
            float2 k2 = make_float2(kb.x, kb.y), k3 = make_float2(kb.z, kb.w);
            float p[4];
            #pragma unroll
            for (int i = 0; i < 4; i++) {
                float2 s2 = ffma2(q2[i][0], k0, zero2);
                s2 = ffma2(q2[i][1], k1, s2);
                s2 = ffma2(q2[i][2], k2, s2);
                s2 = ffma2(q2[i][3], k3, s2);
                p[i] = s2.x + s2.y;
            }
            #pragma unroll
            for (int off = 1; off <= 4; off <<= 1)
                #pragma unroll
                for (int i = 0; i < 4; i++)
                    p[i] += __shfl_xor_sync(0xffffffffu, p[i], off);
            if (sub < 4) {
                int i = sub, ri = r0 + i;
                if (c <= ri) sc[w][i][c] = p[i] * 0.125f;
            }
        }
    } else {
        int nch = top0 >> 6;
        for (int k = 0; k <= nch; k++) {
            int top = top0 - 64 * k;
            for (int j0 = 0; j0 < 28; j0 += 4) {
                int rem = urem4(j0 + grp);
                int c = top - rem;
                int cc = c >= 0 ? c : 0;
                const float4* kp = (const float4*)(Kb + (size_t)cc * Ec + sub * 8);
                float4 ka = kp[0], kb = kp[1];
                float2 k0 = make_float2(ka.x, ka.y), k1 = make_float2(ka.z, ka.w);
                float2 k2 = make_float2(kb.x, kb.y), k3 = make_float2(kb.z, kb.w);
                float p[4];
                #pragma unroll
                for (int i = 0; i < 4; i++) {
                    float2 s2 = ffma2(q2[i][0], k0, zero2);
                    s2 = ffma2(q2[i][1], k1, s2);
                    s2 = ffma2(q2[i][2], k2, s2);
                    s2 = ffma2(q2[i][3], k3, s2);
                    p[i] = s2.x + s2.y;
                }
                #pragma unroll
                for (int off = 1; off <= 4; off <<= 1)
                    #pragma unroll
                    for (int i = 0; i < 4; i++)
                        p[i] += __shfl_xor_sync(0xffffffffu, p[i], off);
                if (sub < 4) {
                    int i = sub, ri = r0 + i;
                    int s = rem - (3 - i);
                    if (member_sp(ri, s, c))
                        sc[w][i][12 * k + rank_of(s)] = p[i] * 0.125f;
                }
            }
        }
    }
    __syncwarp();

    // ---- Phase 2+3: per-row softmax + scatter normalized weights ----
    #pragma unroll
    for (int i = 0; i < 4; i++) {
        int ri = r0 + i;
        int jl = ri & 63;
        int npos = dense ? (ri + 1) : (12 * (ri >> 6) + 12);
        float m = -1e30f;
        for (int pos = lane; pos < npos; pos += 32) {
            bool valid = true;
            if (!dense) {
                int k = pos / 12, rk = pos - 12 * k;
                int c = ri - 64 * k - s_of_rank(rk);
                valid = (c >= 0) && !(jl < 5 && c == jl);
            }
            if (valid) m = fmaxf(m, sc[w][i][pos]);
        }
        #pragma unroll
        for (int off = 16; off; off >>= 1)
            m = fmaxf(m, __shfl_xor_sync(0xffffffffu, m, off));
        float sum = 0.f;
        for (int pos = lane; pos < npos; pos += 32) {
            bool valid = true;
            if (!dense) {
                int k = pos / 12, rk = pos - 12 * k;
                int c = ri - 64 * k - s_of_rank(rk);
                valid = (c >= 0) && !(jl < 5 && c == jl);
            }
            if (valid) {
                float e = __expf(sc[w][i][pos] - m);
                sc[w][i][pos] = e;
                sum += e;
            }
        }
        #pragma unroll
        for (int off = 16; off; off >>= 1)
            sum += __shfl_xor_sync(0xffffffffu, sum, off);
        float inv = __fdividef(1.f, sum);
        float* wrow = wbase + (size_t)i * Tc;
        for (int pos = lane; pos < npos; pos += 32) {
            bool valid = true; int c = pos;
            if (!dense) {
                int k = pos / 12, rk = pos - 12 * k;
                c = ri - 64 * k - s_of_rank(rk);
                valid = (c >= 0) && !(jl < 5 && c == jl);
            }
            if (valid) {
                float nw = sc[w][i][pos] * inv;
                sc[w][i][pos] = nw;     // keep for PV
                __stwt(&wrow[c], nw);
            }
        }
    }
    __syncwarp();

    // ---- Phase 4: PV, V reused across 4 rows ----
    float2 acc2[4][4];
    #pragma unroll
    for (int i = 0; i < 4; i++)
        #pragma unroll
        for (int jj = 0; jj < 4; jj++) acc2[i][jj] = zero2;

    if (dense) {
        for (int c0 = 0; c0 <= top0; c0 += 4) {
            int c = c0 + grp;
            int cc = c <= top0 ? c : top0;
            const float4* vp = (const float4*)(Vb + (size_t)cc * Ec + sub * 8);
            float4 va = vp[0], vb = vp[1];
            float2 v0 = make_float2(va.x, va.y), v1 = make_float2(va.z, va.w);
            float2 v2 = make_float2(vb.x, vb.y), v3 = make_float2(vb.z, vb.w);
            #pragma unroll
            for (int i = 0; i < 4; i++) {
                int ri = r0 + i;
                if (c <= ri) {
                    float wg = sc[w][i][c];
                    float2 w2 = make_float2(wg, wg);
                    acc2[i][0] = ffma2(w2, v0, acc2[i][0]);
                    acc2[i][1] = ffma2(w2, v1, acc2[i][1]);
                    acc2[i][2] = ffma2(w2, v2, acc2[i][2]);
                    acc2[i][3] = ffma2(w2, v3, acc2[i][3]);
                }
            }
        }
    } else {
        int nch = top0 >> 6;
        for (int k = 0; k <= nch; k++) {
            int top = top0 - 64 * k;
            for (int j0 = 0; j0 < 28; j0 += 4) {
                int rem = urem4(j0 + grp);
                int c = top - rem;
                int cc = c >= 0 ? c : 0;
                const float4* vp = (const float4*)(Vb + (size_t)cc * Ec + sub * 8);
                float4 va = vp[0], vb = vp[1];
                float2 v0 = make_float2(va.x, va.y), v1 = make_float2(va.z, va.w);
                float2 v2 = make_float2(vb.x, vb.y), v3 = make_float2(vb.z, vb.w);
                #pragma unroll
                for (int i = 0; i < 4; i++) {
                    int ri = r0 + i;
                    int s = rem - (3 - i);
                    if (member_sp(ri, s, c)) {
                        float wg = sc[w][i][12 * k + rank_of(s)];
                        float2 w2 = make_float2(wg, wg);
                        acc2[i][0] = ffma2(w2, v0, acc2[i][0]);
                        acc2[i][1] = ffma2(w2, v1, acc2[i][1]);
                        acc2[i][2] = ffma2(w2, v2, acc2[i][2]);
                        acc2[i][3] = ffma2(w2, v3, acc2[i][3]);
                    }
                }
            }
        }
    }
    // reduce partial accumulators across the 4 column-groups
    #pragma unroll
    for (int off = 8; off <= 16; off <<= 1)
        #pragma unroll
        for (int i = 0; i < 4; i++)
            #pragma unroll
            for (int jj = 0; jj < 4; jj++) {
                float2 o = shfl_xor_f2(acc2[i][jj], off);
                acc2[i][jj].x += o.x; acc2[i][jj].y += o.y;
            }
    if (grp == 0) {
        #pragma unroll
        for (int i = 0; i < 4; i++) {
            float* dst = g_ATT + ((size_t)bh * Tc + r0 + i) * Ec + sub * 8;
            ((float4*)dst)[0] = make_float4(acc2[i][0].x, acc2[i][0].y,
                                            acc2[i][1].x, acc2[i][1].y);
            ((float4*)dst)[1] = make_float4(acc2[i][2].x, acc2[i][2].y,
                                            acc2[i][3].x, acc2[i][3].y);
        }
    }
}

// ---------------------------------------------------------------------------
// Output projection: out[b,t,:] = attn_flat[b,t,:] @ Wp + bp
// ---------------------------------------------------------------------------
__global__ void proj_out(const float* __restrict__ Wp,
                         const float* __restrict__ bp,
                         float* __restrict__ out) {
    __shared__ float as[4][520];
    int base_bt = blockIdx.x * 4;
    int tid = threadIdx.x;   // 256
    for (int idx = tid; idx < 4 * 512; idx += 256) {
        int rr = idx >> 9, c = idx & 511;
        int bt = base_bt + rr;
        int b = bt / Tc, t = bt % Tc;
        int h = c >> 6, e = c & 63;
        as[rr][c] = g_ATT[(((size_t)b * Hc + h) * Tc + t) * Ec + e];
    }
    __syncthreads();
    int rr = tid >> 6, eo = tid & 63;
    float acc = bp[eo];
    for (int c = 0; c < 512; c++)
        acc += as[rr][c] * Wp[(size_t)c * Ec + eo];
    out[(size_t)(base_bt + rr) * Ec + eo] = acc;
}

// ---------------------------------------------------------------------------
extern "C" void kernel_launch(void* const* d_in, const int* in_sizes, int n_in,
                              void* d_out, int out_size) {
    const float* x    = (const float*)d_in[0];
    const float* Wqk  = (const float*)d_in[1];
    const float* bqk  = (const float*)d_in[2];
    const float* Wv   = (const float*)d_in[3];
    const float* bv   = (const float*)d_in[4];
    const float* Wp   = (const float*)d_in[5];
    const float* bp   = (const float*)d_in[6];
    // d_in[7] (mask) unused: membership regenerated by closed-form predicate.

    float* out = (float*)d_out;
    float* weights = out + (size_t)Bc * Tc * Ec;  // attn_weights after out

    proj_v<<<Bc * Tc / 8, 128>>>(x, Wv, bv);
    dim3 gqk(Tc / 64, 1024 / 16, Bc);
    proj_qk<<<gqk, 128>>>(x, Wqk, bqk);
    attn3<<<dim3(128, 32), 128>>>(weights);
    proj_out<<<Bc * Tc / 4, 256>>>(Wp, bp, out);
}

// round 6
// speedup vs baseline: 1.6369x; 1.2742x over previous
#include <cuda_runtime.h>
#include <math.h>

#define Bc 4
#define Tc 2048
#define Ec 64
#define Hc 8
#define QLc 6
#define BHc (Bc*Hc)
#define CAP 416          // max active columns per row (analysis bound: 384)

__device__ float g_Q[BHc*Tc*Ec];     // [b,h,t,e]
__device__ float g_K[BHc*Tc*Ec];
__device__ float g_V[BHc*Tc*Ec];
__device__ float g_ATT[BHc*Tc*Ec];
__device__ unsigned short g_cols[Tc*CAP];
__device__ int g_cnt[Tc];

// ---- f32x2 packed FMA (PTX-only; two independent exact fp32 FMAs) ----
__device__ __forceinline__ float2 ffma2(float2 a, float2 b, float2 c) {
    float2 d;
    asm("fma.rn.f32x2 %0, %1, %2, %3;"
        : "=l"(*(unsigned long long*)&d)
        : "l"(*(unsigned long long*)&a),
          "l"(*(unsigned long long*)&b),
          "l"(*(unsigned long long*)&c));
    return d;
}

// ---------------------------------------------------------------------------
// Per-row active-column lists, replicating _row_mask(index, 64, 2048) exactly.
// ---------------------------------------------------------------------------
__global__ void build_cols() {
    int row = blockIdx.x * blockDim.x + threadIdx.x;
    if (row >= Tc) return;
    const int log_l = 6, sub = 64;
    unsigned short* out = g_cols + row * CAP;

    if ((Tc / sub) * 2 * log_l > row) {           // row < 384: dense causal
        for (int j = 0; j <= row; j++) out[j] = (unsigned short)j;
        g_cnt[row] = row + 1;
        return;
    }
    unsigned short tmp[CAP];
    int cnt = 0;
    int index = row;
    while (index >= 0) {
        if (index - log_l + 1 < 0) {
            for (int j = index - 1; j >= 0; j--) tmp[cnt++] = (unsigned short)j;
            break;
        }
        for (int j = index; j >= index - log_l + 1; j--)
            tmp[cnt++] = (unsigned short)j;
        for (int i = 0; i < log_l; i++) {
            int ni = index - log_l + 1 - (1 << i);
            if (index - ni <= sub && ni >= 0) tmp[cnt++] = (unsigned short)ni;
        }
        index -= sub;
    }
    for (int j = 0; j < cnt; j++) out[j] = tmp[cnt - 1 - j];
    g_cnt[row] = cnt;
}

// ---------------------------------------------------------------------------
// V projection, tiled: block = 8 bt-rows x 512 outputs, 128 threads.
// ---------------------------------------------------------------------------
__global__ void proj_v(const float* __restrict__ x,
                       const float* __restrict__ Wv,
                       const float* __restrict__ bv) {
    __shared__ float xs[8][64];
    int bt0 = blockIdx.x * 8;
    int tid = threadIdx.x;    // 128
    {
        int m = tid >> 4, i = (tid << 2) & 63;
        *(float4*)&xs[m][i] = *(const float4*)(x + (size_t)(bt0 + m) * Ec + i);
    }
    __syncthreads();
    int nc = tid * 4;
    float2 acc[8][2];
    #pragma unroll
    for (int m = 0; m < 8; m++) { acc[m][0] = make_float2(0.f,0.f); acc[m][1] = make_float2(0.f,0.f); }
    for (int i = 0; i < 64; i++) {
        float4 w4 = *(const float4*)(Wv + (size_t)i * 512 + nc);
        float2 wa = make_float2(w4.x, w4.y), wb = make_float2(w4.z, w4.w);
        #pragma unroll
        for (int m = 0; m < 8; m++) {
            float xm = xs[m][i];
            float2 x2 = make_float2(xm, xm);
            acc[m][0] = ffma2(x2, wa, acc[m][0]);
            acc[m][1] = ffma2(x2, wb, acc[m][1]);
        }
    }
    float4 bb4 = *(const float4*)(bv + nc);
    int h = nc >> 6, e = nc & 63;
    int b = bt0 / Tc;
    #pragma unroll
    for (int m = 0; m < 8; m++) {
        int t = (bt0 & (Tc - 1)) + m;
        float4 o = make_float4(acc[m][0].x + bb4.x, acc[m][0].y + bb4.y,
                               acc[m][1].x + bb4.z, acc[m][1].y + bb4.w);
        *(float4*)(g_V + (((size_t)b * Hc + h) * Tc + t) * Ec + e) = o;
    }
}

// ---------------------------------------------------------------------------
// Causal conv1d QK projection (16-ch x 64-t tile, 128 threads, f32x2)
// ---------------------------------------------------------------------------
__global__ void proj_qk(const float* __restrict__ x,
                        const float* __restrict__ Wqk,
                        const float* __restrict__ bqk) {
    __shared__ float Ws[16][385];
    __shared__ float Xs[69][65];
    int b  = blockIdx.z;
    int o0 = blockIdx.y * 16;
    int t0 = blockIdx.x * 64;
    int tid = threadIdx.x;   // 128

    for (int idx = tid; idx < 16 * 384; idx += 128) {
        int oo = idx / 384, kk = idx % 384;
        int j = kk >> 6, i = kk & 63;
        Ws[oo][kk] = Wqk[(size_t)(o0 + oo) * 384 + i * QLc + j];
    }
    for (int idx = tid; idx < 69 * 64; idx += 128) {
        int rr = idx >> 6, i = idx & 63;
        int t = t0 - 5 + rr;
        Xs[rr][i] = (t >= 0) ? x[((size_t)b * Tc + t) * Ec + i] : 0.f;
    }
    __syncthreads();

    int ox = tid & 7;    // 8 groups, 2 channels each
    int tx = tid >> 3;   // 16 groups, 4 timesteps each
    float2 acc2[2][2];
    #pragma unroll
    for (int a = 0; a < 2; a++) { acc2[a][0] = make_float2(0.f,0.f); acc2[a][1] = make_float2(0.f,0.f); }

    for (int kk = 0; kk < 384; kk++) {
        int j = kk >> 6, i = kk & 63;
        float w0 = Ws[ox * 2 + 0][kk];
        float w1 = Ws[ox * 2 + 1][kk];
        float2 w00 = make_float2(w0, w0), w11 = make_float2(w1, w1);
        float x0 = Xs[tx * 4 + 0 + j][i], x1 = Xs[tx * 4 + 1 + j][i];
        float x2 = Xs[tx * 4 + 2 + j][i], x3 = Xs[tx * 4 + 3 + j][i];
        float2 x01 = make_float2(x0, x1), x23 = make_float2(x2, x3);
        acc2[0][0] = ffma2(w00, x01, acc2[0][0]);
        acc2[0][1] = ffma2(w00, x23, acc2[0][1]);
        acc2[1][0] = ffma2(w11, x01, acc2[1][0]);
        acc2[1][1] = ffma2(w11, x23, acc2[1][1]);
    }
    #pragma unroll
    for (int a = 0; a < 2; a++) {
        int ch = o0 + ox * 2 + a;
        float bias = bqk[ch];
        int hh = (ch & 511) >> 6, e = ch & 63;
        float* dst = (ch < 512 ? g_Q : g_K) +
                     ((size_t)b * Hc + hh) * Tc * Ec + e;
        float vals[4] = {acc2[a][0].x, acc2[a][0].y, acc2[a][1].x, acc2[a][1].y};
        #pragma unroll
        for (int bb = 0; bb < 4; bb++) {
            int t = t0 + tx * 4 + bb;
            dst[(size_t)t * Ec] = vals[bb] + bias;
        }
    }
}

// ---------------------------------------------------------------------------
// Sparse masked attention: one warp per query row (R3 shape).
// K loads: 8-lane groups read CONTIGUOUS 128B half-rows (1 line per group
// per LDG -> 2 wavefronts per column-visit, was 4).
// ---------------------------------------------------------------------------
__global__ __launch_bounds__(256) void attn_kernel(float* __restrict__ wout_base) {
    __shared__ float sc[8][CAP];
    int w = threadIdx.x >> 5;
    int lane = threadIdx.x & 31;
    int sub = lane & 7;          // owns contiguous float4 chunk within half-row
    int grp = lane >> 3;         // column group 0..3
    int r = blockIdx.x * 8 + w;
    int bh = blockIdx.y;

    // Q registers: floats [sub*4..sub*4+3] and [32+sub*4..32+sub*4+3]
    const float* Qrow = g_Q + ((size_t)bh * Tc + r) * Ec;
    float4 qa4 = *(const float4*)(Qrow + sub * 4);
    float4 qb4 = *(const float4*)(Qrow + 32 + sub * 4);
    float2 qa = make_float2(qa4.x, qa4.y), qb = make_float2(qa4.z, qa4.w);
    float2 qc = make_float2(qb4.x, qb4.y), qd = make_float2(qb4.z, qb4.w);

    // Zero this row of the weights output (streaming; replaces memset)
    float* wout = wout_base + ((size_t)bh * Tc + r) * Tc;
    float4 z4 = make_float4(0.f, 0.f, 0.f, 0.f);
    #pragma unroll
    for (int s = 0; s < 16; s++)
        __stwt(&((float4*)wout)[s * 32 + lane], z4);

    int cnt = g_cnt[r];
    const unsigned short* cl = g_cols + r * CAP;
    const float* Kb = g_K + (size_t)bh * Tc * Ec;
    const float2 zero2 = make_float2(0.f, 0.f);

    // Scores: 4 columns per step; 8 lanes per column, contiguous chunks.
    float m = -1e30f;
    for (int j0 = 0; j0 < cnt; j0 += 4) {
        int jj = j0 + grp;
        int c = cl[jj < cnt ? jj : cnt - 1];
        const float* krow = Kb + (size_t)c * Ec;
        float4 ka4 = *(const float4*)(krow + sub * 4);
        float4 kb4 = *(const float4*)(krow + 32 + sub * 4);
        float2 s2 = ffma2(qa, make_float2(ka4.x, ka4.y), zero2);
        s2 = ffma2(qb, make_float2(ka4.z, ka4.w), s2);
        s2 = ffma2(qc, make_float2(kb4.x, kb4.y), s2);
        s2 = ffma2(qd, make_float2(kb4.z, kb4.w), s2);
        float p = s2.x + s2.y;
        p += __shfl_down_sync(0xffffffffu, p, 4);
        p += __shfl_down_sync(0xffffffffu, p, 2);
        p += __shfl_down_sync(0xffffffffu, p, 1);
        float s = p * 0.125f;     // 1/sqrt(64)
        if (sub == 0 && jj < cnt) {
            sc[w][jj] = s;
            m = fmaxf(m, s);
        }
    }
    #pragma unroll
    for (int off = 16; off; off >>= 1)
        m = fmaxf(m, __shfl_xor_sync(0xffffffffu, m, off));
    __syncwarp();

    // exp + sum
    float sum = 0.f;
    for (int jj = lane; jj < cnt; jj += 32) {
        float e = __expf(sc[w][jj] - m);
        sc[w][jj] = e;
        sum += e;
    }
    #pragma unroll
    for (int off = 16; off; off >>= 1)
        sum += __shfl_xor_sync(0xffffffffu, sum, off);
    float inv = __fdividef(1.f, sum);
    __syncwarp();

    // scattered weight writes (row already zeroed by this warp)
    for (int jj = lane; jj < cnt; jj += 32)
        __stwt(&wout[cl[jj]], sc[w][jj] * inv);

    // PV accumulate: each lane owns a float2 of e-dims (contiguous 256B/warp)
    const float* Vb = g_V + (size_t)bh * Tc * Ec;
    float2 oacc = zero2;
    int jj = 0;
    for (; jj + 4 <= cnt; jj += 4) {
        #pragma unroll
        for (int u = 0; u < 4; u++) {
            float wg = sc[w][jj + u];
            float2 w2 = make_float2(wg, wg);
            float2 v2 = ((const float2*)(Vb + (size_t)cl[jj + u] * Ec))[lane];
            oacc = ffma2(w2, v2, oacc);
        }
    }
    for (; jj < cnt; jj++) {
        float wg = sc[w][jj];
        float2 w2 = make_float2(wg, wg);
        float2 v2 = ((const float2*)(Vb + (size_t)cl[jj] * Ec))[lane];
        oacc = ffma2(w2, v2, oacc);
    }
    float* ar = g_ATT + ((size_t)bh * Tc + r) * Ec;
    ((float2*)ar)[lane] = make_float2(oacc.x * inv, oacc.y * inv);
}

// ---------------------------------------------------------------------------
// Output projection: out[b,t,:] = attn_flat[b,t,:] @ Wp + bp
// ---------------------------------------------------------------------------
__global__ void proj_out(const float* __restrict__ Wp,
                         const float* __restrict__ bp,
                         float* __restrict__ out) {
    __shared__ float as[4][520];
    int base_bt = blockIdx.x * 4;
    int tid = threadIdx.x;   // 256
    for (int idx = tid; idx < 4 * 512; idx += 256) {
        int rr = idx >> 9, c = idx & 511;
        int bt = base_bt + rr;
        int b = bt / Tc, t = bt % Tc;
        int h = c >> 6, e = c & 63;
        as[rr][c] = g_ATT[(((size_t)b * Hc + h) * Tc + t) * Ec + e];
    }
    __syncthreads();
    int rr = tid >> 6, eo = tid & 63;
    float acc = bp[eo];
    for (int c = 0; c < 512; c++)
        acc += as[rr][c] * Wp[(size_t)c * Ec + eo];
    out[(size_t)(base_bt + rr) * Ec + eo] = acc;
}

// ---------------------------------------------------------------------------
extern "C" void kernel_launch(void* const* d_in, const int* in_sizes, int n_in,
                              void* d_out, int out_size) {
    const float* x    = (const float*)d_in[0];
    const float* Wqk  = (const float*)d_in[1];
    const float* bqk  = (const float*)d_in[2];
    const float* Wv   = (const float*)d_in[3];
    const float* bv   = (const float*)d_in[4];
    const float* Wp   = (const float*)d_in[5];
    const float* bp   = (const float*)d_in[6];
    // d_in[7] (mask) unused: regenerated on-device (dtype-agnostic).

    float* out = (float*)d_out;
    float* weights = out + (size_t)Bc * Tc * Ec;  // attn_weights after out

    build_cols<<<(Tc + 127) / 128, 128>>>();
    proj_v<<<Bc * Tc / 8, 128>>>(x, Wv, bv);
    dim3 gqk(Tc / 64, 1024 / 16, Bc);
    proj_qk<<<gqk, 128>>>(x, Wqk, bqk);
    dim3 ga(Tc / 8, BHc);
    attn_kernel<<<ga, 256>>>(weights);
    proj_out<<<Bc * Tc / 4, 256>>>(Wp, bp, out);
}

// round 7
// speedup vs baseline: 1.9915x; 1.2166x over previous
#include <cuda_runtime.h>
#include <math.h>

#define Bc 4
#define Tc 2048
#define Ec 64
#define Hc 8
#define QLc 6
#define BHc (Bc*Hc)
#define CAP 416          // max active columns per row (analysis bound: 384)

__device__ float g_Q[BHc*Tc*Ec];     // [b,h,t,e]
__device__ float g_K[BHc*Tc*Ec];
__device__ float g_V[BHc*Tc*Ec];
__device__ float g_ATT[BHc*Tc*Ec];
__device__ float g_Wt[384*1024];     // transposed Wqk: [kk][ch], kk = i*6+j
__device__ unsigned short g_cols[Tc*CAP];
__device__ int g_cnt[Tc];

// ---- f32x2 packed FMA (PTX-only; two independent exact fp32 FMAs) ----
__device__ __forceinline__ float2 ffma2(float2 a, float2 b, float2 c) {
    float2 d;
    asm("fma.rn.f32x2 %0, %1, %2, %3;"
        : "=l"(*(unsigned long long*)&d)
        : "l"(*(unsigned long long*)&a),
          "l"(*(unsigned long long*)&b),
          "l"(*(unsigned long long*)&c));
    return d;
}

// ---------------------------------------------------------------------------
// Per-row active-column lists, replicating _row_mask(index, 64, 2048) exactly.
// ---------------------------------------------------------------------------
__global__ void build_cols() {
    int row = blockIdx.x * blockDim.x + threadIdx.x;
    if (row >= Tc) return;
    const int log_l = 6, sub = 64;
    unsigned short* out = g_cols + row * CAP;

    if ((Tc / sub) * 2 * log_l > row) {           // row < 384: dense causal
        for (int j = 0; j <= row; j++) out[j] = (unsigned short)j;
        g_cnt[row] = row + 1;
        return;
    }
    unsigned short tmp[CAP];
    int cnt = 0;
    int index = row;
    while (index >= 0) {
        if (index - log_l + 1 < 0) {
            for (int j = index - 1; j >= 0; j--) tmp[cnt++] = (unsigned short)j;
            break;
        }
        for (int j = index; j >= index - log_l + 1; j--)
            tmp[cnt++] = (unsigned short)j;
        for (int i = 0; i < log_l; i++) {
            int ni = index - log_l + 1 - (1 << i);
            if (index - ni <= sub && ni >= 0) tmp[cnt++] = (unsigned short)ni;
        }
        index -= sub;
    }
    for (int j = 0; j < cnt; j++) out[j] = tmp[cnt - 1 - j];
    g_cnt[row] = cnt;
}

// ---------------------------------------------------------------------------
// Transpose Wqk [1024][384] -> g_Wt [384][1024]
// ---------------------------------------------------------------------------
__global__ void wt_transpose(const float* __restrict__ Wqk) {
    __shared__ float tile[32][33];
    int ch0 = blockIdx.x * 32;
    int kk0 = blockIdx.y * 32;
    int lx = threadIdx.x & 31, ly = threadIdx.x >> 5;   // 256 threads
    #pragma unroll
    for (int k = 0; k < 4; k++)
        tile[ly + 8 * k][lx] = Wqk[(size_t)(ch0 + ly + 8 * k) * 384 + kk0 + lx];
    __syncthreads();
    #pragma unroll
    for (int k = 0; k < 4; k++)
        g_Wt[(size_t)(kk0 + ly + 8 * k) * 1024 + ch0 + lx] = tile[lx][ly + 8 * k];
}

// ---------------------------------------------------------------------------
// V projection, tiled: block = 8 bt-rows x 512 outputs, 128 threads.
// ---------------------------------------------------------------------------
__global__ void proj_v(const float* __restrict__ x,
                       const float* __restrict__ Wv,
                       const float* __restrict__ bv) {
    __shared__ float xs[8][64];
    int bt0 = blockIdx.x * 8;
    int tid = threadIdx.x;    // 128
    {
        int m = tid >> 4, i = (tid << 2) & 63;
        *(float4*)&xs[m][i] = *(const float4*)(x + (size_t)(bt0 + m) * Ec + i);
    }
    __syncthreads();
    int nc = tid * 4;
    float2 acc[8][2];
    #pragma unroll
    for (int m = 0; m < 8; m++) { acc[m][0] = make_float2(0.f,0.f); acc[m][1] = make_float2(0.f,0.f); }
    for (int i = 0; i < 64; i++) {
        float4 w4 = *(const float4*)(Wv + (size_t)i * 512 + nc);
        float2 wa = make_float2(w4.x, w4.y), wb = make_float2(w4.z, w4.w);
        #pragma unroll
        for (int m = 0; m < 8; m++) {
            float xm = xs[m][i];
            float2 x2 = make_float2(xm, xm);
            acc[m][0] = ffma2(x2, wa, acc[m][0]);
            acc[m][1] = ffma2(x2, wb, acc[m][1]);
        }
    }
    float4 bb4 = *(const float4*)(bv + nc);
    int h = nc >> 6, e = nc & 63;
    int b = bt0 / Tc;
    #pragma unroll
    for (int m = 0; m < 8; m++) {
        int t = (bt0 & (Tc - 1)) + m;
        float4 o = make_float4(acc[m][0].x + bb4.x, acc[m][0].y + bb4.y,
                               acc[m][1].x + bb4.z, acc[m][1].y + bb4.w);
        *(float4*)(g_V + (((size_t)b * Hc + h) * Tc + t) * Ec + e) = o;
    }
}

// ---------------------------------------------------------------------------
// Causal conv1d QK projection v2: 64t x 64ch block GEMM over K=384 (i,j).
// XsT[i][s] = x[t0-5+s][i]; W staged from g_Wt in 96-row chunks.
// Thread: 4t x 4ch, FFMA2 over ch-pairs, conv shifts via register window.
// ---------------------------------------------------------------------------
__global__ __launch_bounds__(256) void proj_qk2(const float* __restrict__ x,
                                                const float* __restrict__ bqk) {
    __shared__ float XsT[64][72];      // [i][s], row = 288B (16B aligned)
    __shared__ float Wc[96][64];       // [kk_local][ch_local]
    int b   = blockIdx.z;
    int ch0 = blockIdx.y * 64;
    int t0  = blockIdx.x * 64;
    int tid = threadIdx.x;             // 256
    int tx = tid & 15;                 // 4 timesteps each
    int cx = tid >> 4;                 // 4 channels each

    // Stage x transposed (69 s-rows x 64 i)
    for (int idx = tid; idx < 69 * 16; idx += 256) {
        int s = idx >> 4, i4 = (idx & 15) * 4;
        int t = t0 - 5 + s;
        float4 v = (t >= 0) ? *(const float4*)(x + ((size_t)b * Tc + t) * Ec + i4)
                            : make_float4(0.f, 0.f, 0.f, 0.f);
        XsT[i4 + 0][s] = v.x; XsT[i4 + 1][s] = v.y;
        XsT[i4 + 2][s] = v.z; XsT[i4 + 3][s] = v.w;
    }

    float2 acc2[4][2];   // [t][ch-pair]
    #pragma unroll
    for (int tt = 0; tt < 4; tt++) { acc2[tt][0] = make_float2(0.f,0.f); acc2[tt][1] = make_float2(0.f,0.f); }

    for (int ic = 0; ic < 4; ic++) {
        __syncthreads();
        // stage W chunk: kk in [ic*96, ic*96+96)
        for (int idx = tid; idx < 96 * 16; idx += 256) {
            int row = idx >> 4, c4 = (idx & 15) * 4;
            *(float4*)&Wc[row][c4] =
                *(const float4*)(g_Wt + (size_t)(ic * 96 + row) * 1024 + ch0 + c4);
        }
        __syncthreads();
        #pragma unroll 4
        for (int ii = 0; ii < 16; ii++) {
            float4 A  = *(float4*)&XsT[ic * 16 + ii][tx * 4];
            float4 Bf = *(float4*)&XsT[ic * 16 + ii][tx * 4 + 4];
            float c8  = XsT[ic * 16 + ii][tx * 4 + 8];
            float win[9] = {A.x, A.y, A.z, A.w, Bf.x, Bf.y, Bf.z, Bf.w, c8};
            #pragma unroll
            for (int j = 0; j < 6; j++) {
                float4 w4 = *(float4*)&Wc[ii * 6 + j][cx * 4];
                float2 wp0 = make_float2(w4.x, w4.y);
                float2 wp1 = make_float2(w4.z, w4.w);
                #pragma unroll
                for (int tt = 0; tt < 4; tt++) {
                    float xv = win[j + tt];
                    float2 xb = make_float2(xv, xv);
                    acc2[tt][0] = ffma2(xb, wp0, acc2[tt][0]);
                    acc2[tt][1] = ffma2(xb, wp1, acc2[tt][1]);
                }
            }
        }
    }

    // Epilogue: ch block is 4 contiguous e within one head
    int ch = ch0 + cx * 4;
    float4 b4 = *(const float4*)(bqk + ch);
    int hh = (ch & 511) >> 6, e0 = ch & 63;
    float* base = (ch < 512 ? g_Q : g_K) + ((size_t)b * Hc + hh) * Tc * Ec + e0;
    #pragma unroll
    for (int tt = 0; tt < 4; tt++) {
        int t = t0 + tx * 4 + tt;
        float4 o = make_float4(acc2[tt][0].x + b4.x, acc2[tt][0].y + b4.y,
                               acc2[tt][1].x + b4.z, acc2[tt][1].y + b4.w);
        *(float4*)(base + (size_t)t * Ec) = o;
    }
}

// ---------------------------------------------------------------------------
// Sparse masked attention: one warp per query row (unchanged from R6 win).
// ---------------------------------------------------------------------------
__global__ __launch_bounds__(256) void attn_kernel(float* __restrict__ wout_base) {
    __shared__ float sc[8][CAP];
    int w = threadIdx.x >> 5;
    int lane = threadIdx.x & 31;
    int sub = lane & 7;
    int grp = lane >> 3;
    int r = blockIdx.x * 8 + w;
    int bh = blockIdx.y;

    const float* Qrow = g_Q + ((size_t)bh * Tc + r) * Ec;
    float4 qa4 = *(const float4*)(Qrow + sub * 4);
    float4 qb4 = *(const float4*)(Qrow + 32 + sub * 4);
    float2 qa = make_float2(qa4.x, qa4.y), qb = make_float2(qa4.z, qa4.w);
    float2 qc = make_float2(qb4.x, qb4.y), qd = make_float2(qb4.z, qb4.w);

    float* wout = wout_base + ((size_t)bh * Tc + r) * Tc;
    float4 z4 = make_float4(0.f, 0.f, 0.f, 0.f);
    #pragma unroll
    for (int s = 0; s < 16; s++)
        __stwt(&((float4*)wout)[s * 32 + lane], z4);

    int cnt = g_cnt[r];
    const unsigned short* cl = g_cols + r * CAP;
    const float* Kb = g_K + (size_t)bh * Tc * Ec;
    const float2 zero2 = make_float2(0.f, 0.f);

    float m = -1e30f;
    for (int j0 = 0; j0 < cnt; j0 += 4) {
        int jj = j0 + grp;
        int c = cl[jj < cnt ? jj : cnt - 1];
        const float* krow = Kb + (size_t)c * Ec;
        float4 ka4 = *(const float4*)(krow + sub * 4);
        float4 kb4 = *(const float4*)(krow + 32 + sub * 4);
        float2 s2 = ffma2(qa, make_float2(ka4.x, ka4.y), zero2);
        s2 = ffma2(qb, make_float2(ka4.z, ka4.w), s2);
        s2 = ffma2(qc, make_float2(kb4.x, kb4.y), s2);
        s2 = ffma2(qd, make_float2(kb4.z, kb4.w), s2);
        float p = s2.x + s2.y;
        p += __shfl_down_sync(0xffffffffu, p, 4);
        p += __shfl_down_sync(0xffffffffu, p, 2);
        p += __shfl_down_sync(0xffffffffu, p, 1);
        float s = p * 0.125f;
        if (sub == 0 && jj < cnt) {
            sc[w][jj] = s;
            m = fmaxf(m, s);
        }
    }
    #pragma unroll
    for (int off = 16; off; off >>= 1)
        m = fmaxf(m, __shfl_xor_sync(0xffffffffu, m, off));
    __syncwarp();

    float sum = 0.f;
    for (int jj = lane; jj < cnt; jj += 32) {
        float e = __expf(sc[w][jj] - m);
        sc[w][jj] = e;
        sum += e;
    }
    #pragma unroll
    for (int off = 16; off; off >>= 1)
        sum += __shfl_xor_sync(0xffffffffu, sum, off);
    float inv = __fdividef(1.f, sum);
    __syncwarp();

    for (int jj = lane; jj < cnt; jj += 32)
        __stwt(&wout[cl[jj]], sc[w][jj] * inv);

    const float* Vb = g_V + (size_t)bh * Tc * Ec;
    float2 oacc = zero2;
    int jj = 0;
    for (; jj + 4 <= cnt; jj += 4) {
        #pragma unroll
        for (int u = 0; u < 4; u++) {
            float wg = sc[w][jj + u];
            float2 w2 = make_float2(wg, wg);
            float2 v2 = ((const float2*)(Vb + (size_t)cl[jj + u] * Ec))[lane];
            oacc = ffma2(w2, v2, oacc);
        }
    }
    for (; jj < cnt; jj++) {
        float wg = sc[w][jj];
        float2 w2 = make_float2(wg, wg);
        float2 v2 = ((const float2*)(Vb + (size_t)cl[jj] * Ec))[lane];
        oacc = ffma2(w2, v2, oacc);
    }
    float* ar = g_ATT + ((size_t)bh * Tc + r) * Ec;
    ((float2*)ar)[lane] = make_float2(oacc.x * inv, oacc.y * inv);
}

// ---------------------------------------------------------------------------
// Output projection v2: 32bt x 64eo block GEMM over K=512 in 8 chunks.
// ---------------------------------------------------------------------------
__global__ __launch_bounds__(256) void proj_out2(const float* __restrict__ Wp,
                                                 const float* __restrict__ bp,
                                                 float* __restrict__ out) {
    __shared__ float asT[64][36];    // [e_local][m], row = 144B (16B aligned)
    __shared__ float wp[64][68];     // [e_local][eo], row = 272B (16B aligned)
    int bt0 = blockIdx.x * 32;
    int b = bt0 / Tc, t0 = bt0 & (Tc - 1);
    int tid = threadIdx.x;           // 256
    int ex = tid & 15;               // 4 eo each
    int mx = tid >> 4;               // 2 bt each

    float2 acc2[2][2];
    acc2[0][0] = make_float2(0.f,0.f); acc2[0][1] = make_float2(0.f,0.f);
    acc2[1][0] = make_float2(0.f,0.f); acc2[1][1] = make_float2(0.f,0.f);

    for (int cc = 0; cc < 8; cc++) {    // cc = head index = K chunk
        __syncthreads();
        for (int idx = tid; idx < 32 * 16; idx += 256) {
            int m = idx >> 4, e4 = (idx & 15) * 4;
            float4 v = *(const float4*)(g_ATT +
                (((size_t)b * Hc + cc) * Tc + t0 + m) * Ec + e4);
            asT[e4 + 0][m] = v.x; asT[e4 + 1][m] = v.y;
            asT[e4 + 2][m] = v.z; asT[e4 + 3][m] = v.w;
        }
        for (int idx = tid; idx < 64 * 16; idx += 256) {
            int k = idx >> 4, e4 = (idx & 15) * 4;
            *(float4*)&wp[k][e4] =
                *(const float4*)(Wp + (size_t)(cc * 64 + k) * Ec + e4);
        }
        __syncthreads();
        #pragma unroll 8
        for (int k = 0; k < 64; k++) {
            float2 a2 = *(float2*)&asT[k][mx * 2];
            float4 w4 = *(float4*)&wp[k][ex * 4];
            float2 wp0 = make_float2(w4.x, w4.y);
            float2 wp1 = make_float2(w4.z, w4.w);
            float2 xb0 = make_float2(a2.x, a2.x);
            float2 xb1 = make_float2(a2.y, a2.y);
            acc2[0][0] = ffma2(xb0, wp0, acc2[0][0]);
            acc2[0][1] = ffma2(xb0, wp1, acc2[0][1]);
            acc2[1][0] = ffma2(xb1, wp0, acc2[1][0]);
            acc2[1][1] = ffma2(xb1, wp1, acc2[1][1]);
        }
    }
    float4 bp4 = *(const float4*)(bp + ex * 4);
    #pragma unroll
    for (int u = 0; u < 2; u++) {
        int t = t0 + mx * 2 + u;
        float4 o = make_float4(acc2[u][0].x + bp4.x, acc2[u][0].y + bp4.y,
                               acc2[u][1].x + bp4.z, acc2[u][1].y + bp4.w);
        *(float4*)(out + ((size_t)b * Tc + t) * Ec + ex * 4) = o;
    }
}

// ---------------------------------------------------------------------------
extern "C" void kernel_launch(void* const* d_in, const int* in_sizes, int n_in,
                              void* d_out, int out_size) {
    const float* x    = (const float*)d_in[0];
    const float* Wqk  = (const float*)d_in[1];
    const float* bqk  = (const float*)d_in[2];
    const float* Wv   = (const float*)d_in[3];
    const float* bv   = (const float*)d_in[4];
    const float* Wp   = (const float*)d_in[5];
    const float* bp   = (const float*)d_in[6];
    // d_in[7] (mask) unused: regenerated on-device (dtype-agnostic).

    float* out = (float*)d_out;
    float* weights = out + (size_t)Bc * Tc * Ec;  // attn_weights after out

    build_cols<<<(Tc + 127) / 128, 128>>>();
    wt_transpose<<<dim3(32, 12), 256>>>(Wqk);
    proj_v<<<Bc * Tc / 8, 128>>>(x, Wv, bv);
    proj_qk2<<<dim3(Tc / 64, 16, Bc), 256>>>(x, bqk);
    attn_kernel<<<dim3(Tc / 8, BHc), 256>>>(weights);
    proj_out2<<<Bc * Tc / 32, 256>>>(Wp, bp, out);
}

// round 8
// speedup vs baseline: 1.9971x; 1.0028x over previous
#include <cuda_runtime.h>
#include <math.h>

#define Bc 4
#define Tc 2048
#define Ec 64
#define Hc 8
#define QLc 6
#define BHc (Bc*Hc)
#define CAP 416

__device__ float g_Q[BHc*Tc*Ec];     // [b,h,t,e]
__device__ float g_K[BHc*Tc*Ec];
__device__ float g_V[BHc*Tc*Ec];
__device__ float g_ATT[BHc*Tc*Ec];
__device__ float g_Wt[384*1024];     // transposed Wqk: [kk][ch]
__device__ unsigned short g_cols[Tc*CAP];
__device__ int g_cnt[Tc];

// ---- f32x2 packed FMA ----
__device__ __forceinline__ float2 ffma2(float2 a, float2 b, float2 c) {
    float2 d;
    asm("fma.rn.f32x2 %0, %1, %2, %3;"
        : "=l"(*(unsigned long long*)&d)
        : "l"(*(unsigned long long*)&a),
          "l"(*(unsigned long long*)&b),
          "l"(*(unsigned long long*)&c));
    return d;
}

// ===========================================================================
// Fat prep kernel: blocks [0,1024) proj_v | [1024,1408) wt_transpose |
// [1408,1416) build_cols.  256 threads each.
// ===========================================================================
__global__ __launch_bounds__(256) void fat_prep(const float* __restrict__ x,
                                                const float* __restrict__ Wv,
                                                const float* __restrict__ bv,
                                                const float* __restrict__ Wqk) {
    int bid = blockIdx.x;
    int tid = threadIdx.x;
    if (bid < 1024) {
        // ---- proj_v: 8 bt-rows, 256 threads, 2 outputs each ----
        __shared__ float xs[8][64];
        int bt0 = bid * 8;
        if (tid < 128) {
            int m = tid >> 4, i = (tid << 2) & 63;
            *(float4*)&xs[m][i] = *(const float4*)(x + (size_t)(bt0 + m) * Ec + i);
        }
        __syncthreads();
        int nc = tid * 2;
        float2 acc[8];
        #pragma unroll
        for (int m = 0; m < 8; m++) acc[m] = make_float2(0.f, 0.f);
        for (int i = 0; i < 64; i++) {
            float2 w2 = *(const float2*)(Wv + (size_t)i * 512 + nc);
            #pragma unroll
            for (int m = 0; m < 8; m++) {
                float xm = xs[m][i];
                acc[m] = ffma2(make_float2(xm, xm), w2, acc[m]);
            }
        }
        float2 b2 = *(const float2*)(bv + nc);
        int h = nc >> 6, e = nc & 63;
        int b = bt0 / Tc;
        #pragma unroll
        for (int m = 0; m < 8; m++) {
            int t = (bt0 & (Tc - 1)) + m;
            *(float2*)(g_V + (((size_t)b * Hc + h) * Tc + t) * Ec + e) =
                make_float2(acc[m].x + b2.x, acc[m].y + b2.y);
        }
    } else if (bid < 1408) {
        // ---- transpose Wqk [1024][384] -> g_Wt [384][1024] ----
        __shared__ float tile[32][33];
        int b2 = bid - 1024;
        int ch0 = (b2 & 31) * 32;
        int kk0 = (b2 >> 5) * 32;
        int lx = tid & 31, ly = tid >> 5;
        #pragma unroll
        for (int k = 0; k < 4; k++)
            tile[ly + 8 * k][lx] = Wqk[(size_t)(ch0 + ly + 8 * k) * 384 + kk0 + lx];
        __syncthreads();
        #pragma unroll
        for (int k = 0; k < 4; k++)
            g_Wt[(size_t)(kk0 + ly + 8 * k) * 1024 + ch0 + lx] = tile[lx][ly + 8 * k];
    } else {
        // ---- build_cols: replicate _row_mask(row, 64, 2048) ----
        int row = (bid - 1408) * 256 + tid;
        if (row >= Tc) return;
        const int log_l = 6, sub = 64;
        unsigned short* out = g_cols + row * CAP;
        if ((Tc / sub) * 2 * log_l > row) {       // dense causal
            for (int j = 0; j <= row; j++) out[j] = (unsigned short)j;
            g_cnt[row] = row + 1;
            return;
        }
        unsigned short tmp[CAP];
        int cnt = 0;
        int index = row;
        while (index >= 0) {
            if (index - log_l + 1 < 0) {
                for (int j = index - 1; j >= 0; j--) tmp[cnt++] = (unsigned short)j;
                break;
            }
            for (int j = index; j >= index - log_l + 1; j--)
                tmp[cnt++] = (unsigned short)j;
            for (int i = 0; i < log_l; i++) {
                int ni = index - log_l + 1 - (1 << i);
                if (index - ni <= sub && ni >= 0) tmp[cnt++] = (unsigned short)ni;
            }
            index -= sub;
        }
        for (int j = 0; j < cnt; j++) out[j] = tmp[cnt - 1 - j];
        g_cnt[row] = cnt;
    }
}

// ===========================================================================
// Causal conv1d QK projection: 64t x 64ch block GEMM (unchanged from R7)
// ===========================================================================
__global__ __launch_bounds__(256) void proj_qk2(const float* __restrict__ x,
                                                const float* __restrict__ bqk) {
    __shared__ float XsT[64][72];
    __shared__ float Wc[96][64];
    int b   = blockIdx.z;
    int ch0 = blockIdx.y * 64;
    int t0  = blockIdx.x * 64;
    int tid = threadIdx.x;
    int tx = tid & 15;
    int cx = tid >> 4;

    for (int idx = tid; idx < 69 * 16; idx += 256) {
        int s = idx >> 4, i4 = (idx & 15) * 4;
        int t = t0 - 5 + s;
        float4 v = (t >= 0) ? *(const float4*)(x + ((size_t)b * Tc + t) * Ec + i4)
                            : make_float4(0.f, 0.f, 0.f, 0.f);
        XsT[i4 + 0][s] = v.x; XsT[i4 + 1][s] = v.y;
        XsT[i4 + 2][s] = v.z; XsT[i4 + 3][s] = v.w;
    }

    float2 acc2[4][2];
    #pragma unroll
    for (int tt = 0; tt < 4; tt++) { acc2[tt][0] = make_float2(0.f,0.f); acc2[tt][1] = make_float2(0.f,0.f); }

    for (int ic = 0; ic < 4; ic++) {
        __syncthreads();
        for (int idx = tid; idx < 96 * 16; idx += 256) {
            int row = idx >> 4, c4 = (idx & 15) * 4;
            *(float4*)&Wc[row][c4] =
                *(const float4*)(g_Wt + (size_t)(ic * 96 + row) * 1024 + ch0 + c4);
        }
        __syncthreads();
        #pragma unroll 4
        for (int ii = 0; ii < 16; ii++) {
            float4 A  = *(float4*)&XsT[ic * 16 + ii][tx * 4];
            float4 Bf = *(float4*)&XsT[ic * 16 + ii][tx * 4 + 4];
            float c8  = XsT[ic * 16 + ii][tx * 4 + 8];
            float win[9] = {A.x, A.y, A.z, A.w, Bf.x, Bf.y, Bf.z, Bf.w, c8};
            #pragma unroll
            for (int j = 0; j < 6; j++) {
                float4 w4 = *(float4*)&Wc[ii * 6 + j][cx * 4];
                float2 wp0 = make_float2(w4.x, w4.y);
                float2 wp1 = make_float2(w4.z, w4.w);
                #pragma unroll
                for (int tt = 0; tt < 4; tt++) {
                    float xv = win[j + tt];
                    float2 xb = make_float2(xv, xv);
                    acc2[tt][0] = ffma2(xb, wp0, acc2[tt][0]);
                    acc2[tt][1] = ffma2(xb, wp1, acc2[tt][1]);
                }
            }
        }
    }
    int ch = ch0 + cx * 4;
    float4 b4 = *(const float4*)(bqk + ch);
    int hh = (ch & 511) >> 6, e0 = ch & 63;
    float* base = (ch < 512 ? g_Q : g_K) + ((size_t)b * Hc + hh) * Tc * Ec + e0;
    #pragma unroll
    for (int tt = 0; tt < 4; tt++) {
        int t = t0 + tx * 4 + tt;
        float4 o = make_float4(acc2[tt][0].x + b4.x, acc2[tt][0].y + b4.y,
                               acc2[tt][1].x + b4.z, acc2[tt][1].y + b4.w);
        *(float4*)(base + (size_t)t * Ec) = o;
    }
}

// ===========================================================================
// Dense attention (rows < 384): GEMM-tiled, 32 rows x full causal width.
// Dynamic smem: scd[32][385] | Qs[32][65] | Kt[64][65]  (74,240 B)
// ===========================================================================
#define SCD(r,c) dsm[(r)*385 + (c)]
#define QSd(r,e) dsm[12320 + (r)*65 + (e)]
#define KTd(c,e) dsm[14400 + (c)*65 + (e)]

__global__ __launch_bounds__(256) void dense_attn(float* __restrict__ wout_base) {
    extern __shared__ float dsm[];
    int rt = blockIdx.x;           // 0..11
    int bh = blockIdx.y;
    int r0 = rt * 32;
    int tid = threadIdx.x;
    int ty = tid >> 5, lane = tid & 31;
    int ntiles = (r0 + 31) / 64 + 1;

    // zero score buffer
    for (int idx = tid; idx < 32 * 385; idx += 256) dsm[idx] = 0.f;

    // load Q tile
    const float* Qb = g_Q + ((size_t)bh * Tc + r0) * Ec;
    for (int idx = tid; idx < 32 * 16; idx += 256) {
        int r = idx >> 4, e4 = (idx & 15) * 4;
        float4 v = *(const float4*)(Qb + (size_t)r * Ec + e4);
        QSd(r, e4 + 0) = v.x; QSd(r, e4 + 1) = v.y;
        QSd(r, e4 + 2) = v.z; QSd(r, e4 + 3) = v.w;
    }

    const float* Kb = g_K + (size_t)bh * Tc * Ec;
    for (int kt = 0; kt < ntiles; kt++) {
        __syncthreads();
        for (int idx = tid; idx < 64 * 16; idx += 256) {
            int c = idx >> 4, e4 = (idx & 15) * 4;
            float4 v = *(const float4*)(Kb + (size_t)(kt * 64 + c) * Ec + e4);
            KTd(c, e4 + 0) = v.x; KTd(c, e4 + 1) = v.y;
            KTd(c, e4 + 2) = v.z; KTd(c, e4 + 3) = v.w;
        }
        __syncthreads();
        float acc[4][2];
        #pragma unroll
        for (int i = 0; i < 4; i++) { acc[i][0] = 0.f; acc[i][1] = 0.f; }
        #pragma unroll 4
        for (int e = 0; e < 64; e++) {
            float kv0 = KTd(lane, e), kv1 = KTd(lane + 32, e);
            #pragma unroll
            for (int i = 0; i < 4; i++) {
                float qv = QSd(ty * 4 + i, e);
                acc[i][0] += qv * kv0;
                acc[i][1] += qv * kv1;
            }
        }
        #pragma unroll
        for (int i = 0; i < 4; i++) {
            int rl = ty * 4 + i, r = r0 + rl;
            int c0 = kt * 64 + lane, c1 = c0 + 32;
            if (c0 <= r) SCD(rl, c0) = acc[i][0] * 0.125f;
            if (c1 <= r) SCD(rl, c1) = acc[i][1] * 0.125f;
        }
    }
    __syncthreads();

    // softmax + full weight-row writes (values then zeros, aligned stripes)
    #pragma unroll
    for (int it = 0; it < 4; it++) {
        int rl = it * 8 + ty, r = r0 + rl, n = r + 1;
        float m = -1e30f;
        for (int c = lane; c < n; c += 32) m = fmaxf(m, SCD(rl, c));
        #pragma unroll
        for (int off = 16; off; off >>= 1)
            m = fmaxf(m, __shfl_xor_sync(0xffffffffu, m, off));
        float sum = 0.f;
        for (int c = lane; c < n; c += 32) {
            float e = __expf(SCD(rl, c) - m);
            SCD(rl, c) = e;
            sum += e;
        }
        #pragma unroll
        for (int off = 16; off; off >>= 1)
            sum += __shfl_xor_sync(0xffffffffu, sum, off);
        float inv = __fdividef(1.f, sum);
        float* wrow = wout_base + ((size_t)bh * Tc + r) * Tc;
        for (int c = lane; c < Tc; c += 32) {
            float v = 0.f;
            if (c < n) { v = SCD(rl, c) * inv; SCD(rl, c) = v; }
            __stwt(&wrow[c], v);
        }
    }
    __syncthreads();

    // PV: V tiles reused across 32 rows
    const float* Vb = g_V + (size_t)bh * Tc * Ec;
    float oacc[4][2];
    #pragma unroll
    for (int i = 0; i < 4; i++) { oacc[i][0] = 0.f; oacc[i][1] = 0.f; }
    for (int kt = 0; kt < ntiles; kt++) {
        __syncthreads();
        for (int idx = tid; idx < 64 * 16; idx += 256) {
            int c = idx >> 4, e4 = (idx & 15) * 4;
            float4 v = *(const float4*)(Vb + (size_t)(kt * 64 + c) * Ec + e4);
            KTd(c, e4 + 0) = v.x; KTd(c, e4 + 1) = v.y;
            KTd(c, e4 + 2) = v.z; KTd(c, e4 + 3) = v.w;
        }
        __syncthreads();
        #pragma unroll 4
        for (int c = 0; c < 64; c++) {
            float v0 = KTd(c, lane), v1 = KTd(c, lane + 32);
            #pragma unroll
            for (int i = 0; i < 4; i++) {
                float wg = SCD(ty * 4 + i, kt * 64 + c);
                oacc[i][0] += wg * v0;
                oacc[i][1] += wg * v1;
            }
        }
    }
    #pragma unroll
    for (int i = 0; i < 4; i++) {
        float* dst = g_ATT + ((size_t)bh * Tc + r0 + ty * 4 + i) * Ec;
        dst[lane] = oacc[i][0];
        dst[lane + 32] = oacc[i][1];
    }
}

// ===========================================================================
// Sparse attention (rows >= 384): one warp per row, unroll-8 with hoisted
// loads for MLP.  Heavy rows scheduled first.
// ===========================================================================
__global__ __launch_bounds__(256) void attn_sparse(float* __restrict__ wout_base) {
    __shared__ float sc[8][CAP];
    int w = threadIdx.x >> 5;
    int lane = threadIdx.x & 31;
    int sub = lane & 7;
    int grp = lane >> 3;
    int r = 2047 - (blockIdx.x * 8 + w);   // 2047 down to 384
    int bh = blockIdx.y;

    const float* Qrow = g_Q + ((size_t)bh * Tc + r) * Ec;
    float4 qa4 = *(const float4*)(Qrow + sub * 4);
    float4 qb4 = *(const float4*)(Qrow + 32 + sub * 4);
    float2 qa = make_float2(qa4.x, qa4.y), qb = make_float2(qa4.z, qa4.w);
    float2 qc = make_float2(qb4.x, qb4.y), qd = make_float2(qb4.z, qb4.w);

    float* wout = wout_base + ((size_t)bh * Tc + r) * Tc;
    float4 z4 = make_float4(0.f, 0.f, 0.f, 0.f);
    #pragma unroll
    for (int s = 0; s < 16; s++)
        __stwt(&((float4*)wout)[s * 32 + lane], z4);

    int cnt = g_cnt[r];
    const unsigned short* cl = g_cols + r * CAP;
    const float* Kb = g_K + (size_t)bh * Tc * Ec;
    const float2 zero2 = make_float2(0.f, 0.f);

    float m = -1e30f;
    int j0 = 0;
    for (; j0 + 8 <= cnt; j0 += 8) {
        int cA = cl[j0 + grp];
        int cB = cl[j0 + 4 + grp];
        const float* krA = Kb + (size_t)cA * Ec;
        const float* krB = Kb + (size_t)cB * Ec;
        float4 a0 = *(const float4*)(krA + sub * 4);
        float4 a1 = *(const float4*)(krA + 32 + sub * 4);
        float4 b0 = *(const float4*)(krB + sub * 4);
        float4 b1 = *(const float4*)(krB + 32 + sub * 4);
        float2 sA = ffma2(qa, make_float2(a0.x, a0.y), zero2);
        float2 sB = ffma2(qa, make_float2(b0.x, b0.y), zero2);
        sA = ffma2(qb, make_float2(a0.z, a0.w), sA);
        sB = ffma2(qb, make_float2(b0.z, b0.w), sB);
        sA = ffma2(qc, make_float2(a1.x, a1.y), sA);
        sB = ffma2(qc, make_float2(b1.x, b1.y), sB);
        sA = ffma2(qd, make_float2(a1.z, a1.w), sA);
        sB = ffma2(qd, make_float2(b1.z, b1.w), sB);
        float pA = sA.x + sA.y, pB = sB.x + sB.y;
        pA += __shfl_down_sync(0xffffffffu, pA, 4);
        pB += __shfl_down_sync(0xffffffffu, pB, 4);
        pA += __shfl_down_sync(0xffffffffu, pA, 2);
        pB += __shfl_down_sync(0xffffffffu, pB, 2);
        pA += __shfl_down_sync(0xffffffffu, pA, 1);
        pB += __shfl_down_sync(0xffffffffu, pB, 1);
        if (sub == 0) {
            float vA = pA * 0.125f, vB = pB * 0.125f;
            sc[w][j0 + grp] = vA;
            sc[w][j0 + 4 + grp] = vB;
            m = fmaxf(m, fmaxf(vA, vB));
        }
    }
    for (; j0 < cnt; j0 += 4) {         // tail (cnt % 8 == 4)
        int jj = j0 + grp;
        int c = cl[jj < cnt ? jj : cnt - 1];
        const float* krow = Kb + (size_t)c * Ec;
        float4 ka4 = *(const float4*)(krow + sub * 4);
        float4 kb4 = *(const float4*)(krow + 32 + sub * 4);
        float2 s2 = ffma2(qa, make_float2(ka4.x, ka4.y), zero2);
        s2 = ffma2(qb, make_float2(ka4.z, ka4.w), s2);
        s2 = ffma2(qc, make_float2(kb4.x, kb4.y), s2);
        s2 = ffma2(qd, make_float2(kb4.z, kb4.w), s2);
        float p = s2.x + s2.y;
        p += __shfl_down_sync(0xffffffffu, p, 4);
        p += __shfl_down_sync(0xffffffffu, p, 2);
        p += __shfl_down_sync(0xffffffffu, p, 1);
        float s = p * 0.125f;
        if (sub == 0 && jj < cnt) {
            sc[w][jj] = s;
            m = fmaxf(m, s);
        }
    }
    #pragma unroll
    for (int off = 16; off; off >>= 1)
        m = fmaxf(m, __shfl_xor_sync(0xffffffffu, m, off));
    __syncwarp();

    float sum = 0.f;
    for (int jj = lane; jj < cnt; jj += 32) {
        float e = __expf(sc[w][jj] - m);
        sc[w][jj] = e;
        sum += e;
    }
    #pragma unroll
    for (int off = 16; off; off >>= 1)
        sum += __shfl_xor_sync(0xffffffffu, sum, off);
    float inv = __fdividef(1.f, sum);
    __syncwarp();

    for (int jj = lane; jj < cnt; jj += 32)
        __stwt(&wout[cl[jj]], sc[w][jj] * inv);

    const float* Vb = g_V + (size_t)bh * Tc * Ec;
    float2 oacc = zero2, oacc2 = zero2;
    int jj = 0;
    for (; jj + 8 <= cnt; jj += 8) {
        float2 v[8];
        #pragma unroll
        for (int u = 0; u < 8; u++)
            v[u] = ((const float2*)(Vb + (size_t)cl[jj + u] * Ec))[lane];
        #pragma unroll
        for (int u = 0; u < 8; u += 2) {
            float w0 = sc[w][jj + u], w1 = sc[w][jj + u + 1];
            oacc  = ffma2(make_float2(w0, w0), v[u], oacc);
            oacc2 = ffma2(make_float2(w1, w1), v[u + 1], oacc2);
        }
    }
    for (; jj < cnt; jj++) {
        float wg = sc[w][jj];
        float2 v2 = ((const float2*)(Vb + (size_t)cl[jj] * Ec))[lane];
        oacc = ffma2(make_float2(wg, wg), v2, oacc);
    }
    float* ar = g_ATT + ((size_t)bh * Tc + r) * Ec;
    ((float2*)ar)[lane] = make_float2((oacc.x + oacc2.x) * inv,
                                      (oacc.y + oacc2.y) * inv);
}

// ===========================================================================
// Output projection: 32bt x 64eo block GEMM over K=512 (unchanged)
// ===========================================================================
__global__ __launch_bounds__(256) void proj_out2(const float* __restrict__ Wp,
                                                 const float* __restrict__ bp,
                                                 float* __restrict__ out) {
    __shared__ float asT[64][36];
    __shared__ float wp[64][68];
    int bt0 = blockIdx.x * 32;
    int b = bt0 / Tc, t0 = bt0 & (Tc - 1);
    int tid = threadIdx.x;
    int ex = tid & 15;
    int mx = tid >> 4;

    float2 acc2[2][2];
    acc2[0][0] = make_float2(0.f,0.f); acc2[0][1] = make_float2(0.f,0.f);
    acc2[1][0] = make_float2(0.f,0.f); acc2[1][1] = make_float2(0.f,0.f);

    for (int cc = 0; cc < 8; cc++) {
        __syncthreads();
        for (int idx = tid; idx < 32 * 16; idx += 256) {
            int m = idx >> 4, e4 = (idx & 15) * 4;
            float4 v = *(const float4*)(g_ATT +
                (((size_t)b * Hc + cc) * Tc + t0 + m) * Ec + e4);
            asT[e4 + 0][m] = v.x; asT[e4 + 1][m] = v.y;
            asT[e4 + 2][m] = v.z; asT[e4 + 3][m] = v.w;
        }
        for (int idx = tid; idx < 64 * 16; idx += 256) {
            int k = idx >> 4, e4 = (idx & 15) * 4;
            *(float4*)&wp[k][e4] =
                *(const float4*)(Wp + (size_t)(cc * 64 + k) * Ec + e4);
        }
        __syncthreads();
        #pragma unroll 8
        for (int k = 0; k < 64; k++) {
            float2 a2 = *(float2*)&asT[k][mx * 2];
            float4 w4 = *(float4*)&wp[k][ex * 4];
            float2 wp0 = make_float2(w4.x, w4.y);
            float2 wp1 = make_float2(w4.z, w4.w);
            float2 xb0 = make_float2(a2.x, a2.x);
            float2 xb1 = make_float2(a2.y, a2.y);
            acc2[0][0] = ffma2(xb0, wp0, acc2[0][0]);
            acc2[0][1] = ffma2(xb0, wp1, acc2[0][1]);
            acc2[1][0] = ffma2(xb1, wp0, acc2[1][0]);
            acc2[1][1] = ffma2(xb1, wp1, acc2[1][1]);
        }
    }
    float4 bp4 = *(const float4*)(bp + ex * 4);
    #pragma unroll
    for (int u = 0; u < 2; u++) {
        int t = t0 + mx * 2 + u;
        float4 o = make_float4(acc2[u][0].x + bp4.x, acc2[u][0].y + bp4.y,
                               acc2[u][1].x + bp4.z, acc2[u][1].y + bp4.w);
        *(float4*)(out + ((size_t)b * Tc + t) * Ec + ex * 4) = o;
    }
}

// ---------------------------------------------------------------------------
extern "C" void kernel_launch(void* const* d_in, const int* in_sizes, int n_in,
                              void* d_out, int out_size) {
    const float* x    = (const float*)d_in[0];
    const float* Wqk  = (const float*)d_in[1];
    const float* bqk  = (const float*)d_in[2];
    const float* Wv   = (const float*)d_in[3];
    const float* bv   = (const float*)d_in[4];
    const float* Wp   = (const float*)d_in[5];
    const float* bp   = (const float*)d_in[6];
    // d_in[7] (mask) unused: regenerated on-device (dtype-agnostic).

    float* out = (float*)d_out;
    float* weights = out + (size_t)Bc * Tc * Ec;

    const int DENSE_SMEM = (32 * 385 + 32 * 65 + 64 * 65) * 4;   // 74,240 B
    cudaFuncSetAttribute(dense_attn,
                         cudaFuncAttributeMaxDynamicSharedMemorySize, DENSE_SMEM);

    fat_prep<<<1416, 256>>>(x, Wv, bv, Wqk);
    proj_qk2<<<dim3(Tc / 64, 16, Bc), 256>>>(x, bqk);
    dense_attn<<<dim3(12, BHc), 256, DENSE_SMEM>>>(weights);
    attn_sparse<<<dim3(208, BHc), 256>>>(weights);
    proj_out2<<<Bc * Tc / 32, 256>>>(Wp, bp, out);
}